// round 15
// baseline (speedup 1.0000x reference)
#include <cuda_runtime.h>
#include <cuda_bf16.h>

#define M 512
#define LINES 1024         // 512 row-lines + 512 col-lines
#define MARGIN 0.2f
#define WPC 4              // warps (lines) per CTA
#define NT (WPC * 32)
#define NGRID (LINES / WPC)
#define FULL 0xffffffffu

#define CNT_SHIFT 40
#define LOW_MASK  ((1ULL << CNT_SHIFT) - 1ULL)
#define FIX_SCALE 1048576.0f           // 2^20
#define FIX_INV   (1.0 / 1048576.0)
#define FIX_OFF   16.0f                // x in (-16,16): (x+16)*2^20 fits 25 bits

__device__ float2 g_partials[LINES];
__device__ int    g_count = 0;         // ticket; reset by the finalizing block

__global__ __launch_bounds__(NT)
void side_kernel(const float* __restrict__ scores,
                 const int* __restrict__ labels,
                 float* __restrict__ out) {
    __shared__ float NVS[WPC][M];                // per-warp negs grouped by bucket
    __shared__ unsigned long long HIST[WPC][32]; // [40,64)=cnt, [0,40)=fix sum(x+16)
    __shared__ float red_m[WPC], red_v[WPC];
    __shared__ bool  is_last;

    const int t    = threadIdx.x;
    const int lane = t & 31;
    const int w    = t >> 5;
    const int line = blockIdx.x * WPC + w;       // 0..1023

    // ---- load 16 elements per lane ----
    float    s[16];
    unsigned pmask = 0;
    if (line < M) {                               // row line: vectorized
        const float4* s4 = (const float4*)(scores + line * M);
        const int4*   l4 = (const int4*)(labels + line * M);
        #pragma unroll
        for (int i = 0; i < 4; i++) {
            float4 v  = s4[lane + 32 * i];
            int4   lb = l4[lane + 32 * i];
            s[4*i+0] = v.x; s[4*i+1] = v.y; s[4*i+2] = v.z; s[4*i+3] = v.w;
            pmask |= (unsigned)(lb.x == 1) << (4*i+0);
            pmask |= (unsigned)(lb.y == 1) << (4*i+1);
            pmask |= (unsigned)(lb.z == 1) << (4*i+2);
            pmask |= (unsigned)(lb.w == 1) << (4*i+3);
        }
    } else {                                      // col line: strided gather
        const int col = line - M;
        #pragma unroll
        for (int i = 0; i < 16; i++) {
            const int e = lane + 32 * i;
            s[i] = scores[e * M + col];
            pmask |= (unsigned)(labels[e * M + col] == 1) << i;
        }
    }

    unsigned long long* H   = HIST[w];
    float*             wNVS = NVS[w];
    H[lane] = 0ULL;
    __syncwarp();

    // ---- histogram: ONE packed atomic per neg; returned count = rank ----
    // monotone bucket floor((x+8)*2) clamped to [0,31]: cross-bucket suffix is
    // exact; same-bucket pairs are handled by direct relu on exact floats.
    int kb[16], rk[16];
    #pragma unroll
    for (int i = 0; i < 16; i++) {
        const bool  pos = (pmask >> i) & 1;
        const float x   = pos ? s[i] : (s[i] + MARGIN);
        int k = __float2int_rd((x + 8.0f) * 2.0f);
        k = max(0, min(31, k));
        kb[i] = k;
        rk[i] = 0;
        if (!pos) {
            unsigned long long v = (unsigned long long)(unsigned)((x + FIX_OFF) * FIX_SCALE);
            unsigned long long old = atomicAdd(&H[k], (1ULL << CNT_SHIFT) | v);
            rk[i] = (int)(old >> CNT_SHIFT);
        }
    }
    __syncwarp();

    // ---- warp scan over 32 buckets (lane owns bucket = lane) ----
    const unsigned long long h0 = H[lane];
    unsigned long long inc = h0;
    #pragma unroll
    for (int o = 1; o < 32; o <<= 1) {
        unsigned long long n = __shfl_up_sync(FULL, inc, o);
        if (lane >= o) inc += n;
    }
    const unsigned long long tot = __shfl_sync(FULL, inc, 31);
    const unsigned long long suf = tot - inc;    // exact field-wise
    const int nn     = (int)(tot >> CNT_SHIFT);
    const int myCnt  = (int)(h0  >> CNT_SHIFT);
    const int myOff  = (int)(inc >> CNT_SHIFT) - myCnt;
    const int sufCnt = (int)(suf >> CNT_SHIFT);
    const float sufSf = (float)((double)(suf & LOW_MASK) * FIX_INV
                                - (double)FIX_OFF * (double)sufCnt);
    // pack per-bucket metadata into one int: off[10] | cnt[10] | sufCnt[10]
    const int meta = (myOff << 20) | (myCnt << 10) | sufCnt;

    // ---- scatter negs by bucket (off via index-shuffle from owning lane) ----
    #pragma unroll
    for (int i = 0; i < 16; i++) {
        const int off = __shfl_sync(FULL, meta, kb[i]) >> 20;
        if (!((pmask >> i) & 1))
            wNVS[off + rk[i]] = s[i] + MARGIN;
    }
    __syncwarp();

    // ---- eval: exact suffix part + same-bucket relu scan ----
    float total = 0.f;
    #pragma unroll
    for (int i = 0; i < 16; i++) {
        const int   mt = __shfl_sync(FULL, meta,  kb[i]);
        const float sS = __shfl_sync(FULL, sufSf, kb[i]);
        const bool  pos = (pmask >> i) & 1;
        const int   off = mt >> 20;
        const int   cnt = pos ? ((mt >> 10) & 1023) : 0;
        float a = fmaf(-(float)(mt & 1023), s[i], sS);
        for (int j = 0; j < cnt; j++)
            a += fmaxf(wNVS[off + j] - s[i], 0.f);
        total += pos ? a : 0.f;
    }

    // ---- warp reduction + per-line mean ----
    #pragma unroll
    for (int o = 16; o > 0; o >>= 1)
        total += __shfl_down_sync(FULL, total, o);
    if (lane == 0) {
        const int   np    = M - nn;
        const bool  valid = (np > 0) && (nn > 0);
        const float cntf  = (float)np * (float)nn;   // exact in fp32
        float2 p;
        p.x = valid ? (total / cntf) : 0.f;
        p.y = valid ? 1.f : 0.f;
        g_partials[line] = p;
        __threadfence();
    }
    __syncthreads();

    if (t == 0)
        is_last = (atomicAdd(&g_count, 1) == NGRID - 1);
    __syncthreads();

    // ---- last block: fixed-order global reduction + finalize ----
    if (is_last) {
        float m = 0.f, vv = 0.f;
        #pragma unroll
        for (int i = t; i < LINES; i += NT) {
            float2 p = g_partials[i];
            m  += p.x;
            vv += p.y;
        }
        #pragma unroll
        for (int o = 16; o > 0; o >>= 1) {
            m  += __shfl_down_sync(FULL, m, o);
            vv += __shfl_down_sync(FULL, vv, o);
        }
        if (lane == 0) { red_m[w] = m; red_v[w] = vv; }
        __syncthreads();
        if (t == 0) {
            float mm = 0.f, vt = 0.f;
            #pragma unroll
            for (int i = 0; i < WPC; i++) { mm += red_m[i]; vt += red_v[i]; }
            out[0] = mm / vt;
            g_count = 0;                    // reset for next graph replay
        }
    }
}

extern "C" void kernel_launch(void* const* d_in, const int* in_sizes, int n_in,
                              void* d_out, int out_size) {
    const float* scores = (const float*)d_in[0];
    const int*   labels = (const int*)d_in[1];
    float* out = (float*)d_out;

    side_kernel<<<NGRID, NT>>>(scores, labels, out);
}

// round 16
// speedup vs baseline: 1.7945x; 1.7945x over previous
#include <cuda_runtime.h>
#include <cuda_bf16.h>

#define M 512
#define NBLK 1024          // 512 row-lines + 512 col-lines
#define MARGIN 0.2f
#define NT 256
#define NB 256             // buckets
#define NW 8               // warps per CTA
#define FULL 0xffffffffu

__device__ float2 g_partials[NBLK];
__device__ int    g_count = 0;     // last-block ticket; reset by the finalizing block

__global__ __launch_bounds__(NT, 8)
void side_kernel(const float* __restrict__ scores,
                 const int* __restrict__ labels,
                 float* __restrict__ out) {
    __shared__ int   whist[NW][NB];   // per-warp private bucket counts (no atomics)
    __shared__ int   wbase[NW][NB];   // cross-warp exclusive base per bucket
    __shared__ int   off[NB];         // bucket start in NVS
    __shared__ int   cnt[NB];         // bucket count
    __shared__ float NVS[M];          // negs grouped by bucket (zero-padded)
    __shared__ float P[M];            // inclusive prefix sums of NVS
    __shared__ int   wci[NW];
    __shared__ float wcf[NW];
    __shared__ float warp_sums[NW];
    __shared__ bool  is_last;

    const int b    = blockIdx.x;
    const int t    = threadIdx.x;
    const int lane = t & 31;
    const int w    = t >> 5;
    const unsigned lt = (1u << lane) - 1u;

    // each thread owns elements t and t+256 of the line
    int idx0, idx1;
    if (b < M) { idx0 = b * M + t;       idx1 = idx0 + NT; }
    else       { idx0 = t * M + (b - M); idx1 = idx0 + NT * M; }

    const float s0 = scores[idx0];
    const float s1 = scores[idx1];
    const bool  p0 = (labels[idx0] == 1);
    const bool  p1 = (labels[idx1] == 1);
    const float x0 = p0 ? s0 : (s0 + MARGIN);
    const float x1 = p1 ? s1 : (s1 + MARGIN);

    // monotone bucket: floor((x+8)*16) clamped to [0,255]. floor+clamp is
    // monotone => cross-bucket suffix part is exact; same-bucket pairs are
    // handled by direct relu on exact floats.
    const int k0 = max(0, min(NB - 1, __float2int_rd((x0 + 8.0f) * 16.0f)));
    const int k1 = max(0, min(NB - 1, __float2int_rd((x1 + 8.0f) * 16.0f)));

    // ---- zero warp-private hist row + NVS padding ----
    {
        int4* row = (int4*)whist[w];          // 256 ints = 64 int4, 2 per lane
        row[lane]      = make_int4(0, 0, 0, 0);
        row[lane + 32] = make_int4(0, 0, 0, 0);
    }
    NVS[t]       = 0.f;
    NVS[t + NT]  = 0.f;
    __syncwarp();

    // ---- match-based warp histogram: ZERO shared-memory atomics ----
    // pos lanes get unique sentinel keys so they never pollute neg groups.
    const int key0 = p0 ? (NB + lane) : k0;
    const unsigned m0 = __match_any_sync(FULL, key0);
    const int g0 = __popc(m0 & lt);                 // rank within warp group
    if (!p0 && g0 == 0) whist[w][k0] = __popc(m0);  // leader writes count
    __syncwarp();

    const int key1 = p1 ? (NB + lane) : k1;
    const unsigned m1 = __match_any_sync(FULL, key1);
    const int g1 = __popc(m1 & lt);
    const int base1 = p1 ? 0 : whist[w][k1];        // element-0 count, same bucket
    __syncwarp();
    if (!p1 && g1 == 0) whist[w][k1] = base1 + __popc(m1);
    __syncthreads();

    // ---- cross-warp bases + int-only block scan over bucket counts ----
    int c = 0;
    #pragma unroll
    for (int ww = 0; ww < NW; ww++) {
        wbase[ww][t] = c;
        c += whist[ww][t];
    }
    cnt[t] = c;

    int inc = c;
    #pragma unroll
    for (int o = 1; o < 32; o <<= 1) {
        int n = __shfl_up_sync(FULL, inc, o);
        if (lane >= o) inc += n;
    }
    if (lane == 31) wci[w] = inc;
    __syncthreads();

    if (t < 32) {
        int ci = (t < NW) ? wci[t] : 0;
        #pragma unroll
        for (int o = 1; o < NW; o <<= 1) {
            int n = __shfl_up_sync(FULL, ci, o);
            if (lane >= o) ci += n;
        }
        if (t < NW) wci[t] = ci;
    }
    __syncthreads();

    const int incC = inc + ((w > 0) ? wci[w - 1] : 0);
    const int nn   = wci[NW - 1];
    off[t] = incC - c;
    __syncthreads();

    // ---- scatter: rank = bucket base + cross-warp base + warp rank ----
    if (!p0) NVS[off[k0] + wbase[w][k0] + g0]         = x0;
    if (!p1) NVS[off[k1] + wbase[w][k1] + base1 + g1] = x1;
    __syncthreads();

    // ---- float block scan over NVS[0..512): replaces all value atomics ----
    const float v0 = NVS[2 * t];
    const float v1 = NVS[2 * t + 1];
    float pinc = v0 + v1;
    #pragma unroll
    for (int o = 1; o < 32; o <<= 1) {
        float n = __shfl_up_sync(FULL, pinc, o);
        if (lane >= o) pinc += n;
    }
    if (lane == 31) wcf[w] = pinc;
    __syncthreads();

    if (t < 32) {
        float fi = (t < NW) ? wcf[t] : 0.f;
        #pragma unroll
        for (int o = 1; o < NW; o <<= 1) {
            float n = __shfl_up_sync(FULL, fi, o);
            if (lane >= o) fi += n;
        }
        if (t < NW) wcf[t] = fi;
    }
    __syncthreads();

    const float incl = pinc + ((w > 0) ? wcf[w - 1] : 0.f);
    P[2 * t + 1] = incl;
    P[2 * t]     = incl - v1;
    const float totF = wcf[NW - 1];
    __syncthreads();

    // ---- eval: exact suffix via prefix array + same-bucket relu ----
    float total = 0.f;
    if (p0) {
        const int o0 = off[k0], j0 = o0 + cnt[k0];
        const float sufS = totF - (j0 ? P[j0 - 1] : 0.f);
        float a = fmaf(-(float)(nn - j0), s0, sufS);
        for (int j = o0; j < j0; j++)              // avg ~1 iteration
            a += fmaxf(NVS[j] - s0, 0.f);
        total += a;
    }
    if (p1) {
        const int o1 = off[k1], j1 = o1 + cnt[k1];
        const float sufS = totF - (j1 ? P[j1 - 1] : 0.f);
        float a = fmaf(-(float)(nn - j1), s1, sufS);
        for (int j = o1; j < j1; j++)
            a += fmaxf(NVS[j] - s1, 0.f);
        total += a;
    }

    // ---- deterministic CTA reduction ----
    #pragma unroll
    for (int o = 16; o > 0; o >>= 1)
        total += __shfl_down_sync(FULL, total, o);
    if (lane == 0) warp_sums[w] = total;
    __syncthreads();

    if (t < 32) {
        float v = (t < NW) ? warp_sums[t] : 0.f;
        #pragma unroll
        for (int o = NW / 2; o > 0; o >>= 1)
            v += __shfl_down_sync(FULL, v, o);
        if (t == 0) {
            const int   np    = M - nn;
            const bool  valid = (np > 0) && (nn > 0);
            const float cntf  = (float)np * (float)nn;   // exact in fp32
            float2 p;
            p.x = valid ? (v / cntf) : 0.f;
            p.y = valid ? 1.f : 0.f;
            g_partials[b] = p;
            __threadfence();
            int cc = atomicAdd(&g_count, 1);
            is_last = (cc == NBLK - 1);
        }
    }
    __syncthreads();

    // ---- last block: fixed-order global reduction + finalize ----
    if (is_last) {
        float m = 0.f, vv = 0.f;
        #pragma unroll
        for (int i = t; i < NBLK; i += NT) {
            float2 p = g_partials[i];
            m  += p.x;
            vv += p.y;
        }
        #pragma unroll
        for (int o = 16; o > 0; o >>= 1) {
            m  += __shfl_down_sync(FULL, m, o);
            vv += __shfl_down_sync(FULL, vv, o);
        }
        if (lane == 0) { warp_sums[w] = m; wcf[w] = vv; }
        __syncthreads();
        if (t < 32) {
            m  = (t < NW) ? warp_sums[t] : 0.f;
            vv = (t < NW) ? wcf[t] : 0.f;
            #pragma unroll
            for (int o = NW / 2; o > 0; o >>= 1) {
                m  += __shfl_down_sync(FULL, m, o);
                vv += __shfl_down_sync(FULL, vv, o);
            }
            if (t == 0) {
                out[0] = m / vv;
                g_count = 0;                    // reset for next graph replay
            }
        }
    }
}

extern "C" void kernel_launch(void* const* d_in, const int* in_sizes, int n_in,
                              void* d_out, int out_size) {
    const float* scores = (const float*)d_in[0];
    const int*   labels = (const int*)d_in[1];
    float* out = (float*)d_out;

    side_kernel<<<NBLK, NT>>>(scores, labels, out);
}

// round 17
// speedup vs baseline: 2.1228x; 1.1830x over previous
#include <cuda_runtime.h>
#include <cuda_bf16.h>

#define M 512
#define NBLK 1024
#define MARGIN 0.2f
#define NT 256
#define NW 8
#define NBUK 1024          // bucket width 1/64 over (-8,8)
#define FULL 0xffffffffu

#define CNT_SHIFT 40
#define LOW_MASK  ((1ULL << CNT_SHIFT) - 1ULL)
#define FIX_SCALE 1048576.0f             // 2^20
#define FIX_INVF  9.5367431640625e-7f    // 2^-20

__device__ float    g_scoresT[M * M];
__device__ unsigned g_rowmask[M * 16];   // bit r of word w: label[row][32w+lane]
__device__ unsigned g_colmask[M * 16];
__device__ float2   g_partials[NBLK];
__device__ int      g_count = 0;

// ---- prep: transpose scores, bit-pack labels in both orientations ----
__global__ void prep_kernel(const float* __restrict__ scores,
                            const int* __restrict__ labels) {
    __shared__ float ts[32][33];
    __shared__ int   tl[32][33];
    const int tx = threadIdx.x, ty = threadIdx.y;
    const int bx = blockIdx.x,  by = blockIdx.y;

    #pragma unroll
    for (int d = 0; d < 4; d++) {
        const int r  = ty + 8 * d;
        const int gr = by * 32 + r, gc = bx * 32 + tx;
        const float v = scores[gr * M + gc];
        const int   L = labels[gr * M + gc];
        ts[r][tx] = v;
        tl[r][tx] = L;
        unsigned m = __ballot_sync(FULL, L == 1);
        if (tx == 0) g_rowmask[gr * 16 + bx] = m;
    }
    __syncthreads();
    #pragma unroll
    for (int d = 0; d < 4; d++) {
        const int c  = ty + 8 * d;
        const int gc = bx * 32 + c, gr = by * 32 + tx;
        g_scoresT[gc * M + gr] = ts[tx][c];              // coalesced write
        unsigned m = __ballot_sync(FULL, tl[tx][c] == 1);
        if (tx == 0) g_colmask[gc * 16 + by] = m;
    }
}

__global__ __launch_bounds__(NT, 8)
void side_kernel(const float* __restrict__ scores,
                 float* __restrict__ out) {
    __shared__ unsigned long long hist[NBUK];   // cnt<<40 | fix20(sum(x+16))
    __shared__ unsigned long long wsc[NW];
    __shared__ float warp_sums[NW];
    __shared__ float wred[NW];
    __shared__ bool  is_last;

    const int b    = blockIdx.x;
    const int t    = threadIdx.x;
    const int lane = t & 31;
    const int w    = t >> 5;

    // ---- coalesced loads (col lines use the transposed copy) ----
    const float*    sp = (b < M) ? (scores + b * M) : (g_scoresT + (b - M) * M);
    const unsigned* mp = (b < M) ? (g_rowmask + b * 16) : (g_colmask + (b - M) * 16);
    const float s0 = sp[t];
    const float s1 = sp[t + NT];
    const bool  p0 = (mp[w] >> lane) & 1;
    const bool  p1 = (mp[w + 8] >> lane) & 1;
    const float x0 = p0 ? s0 : (s0 + MARGIN);
    const float x1 = p1 ? s1 : (s1 + MARGIN);

    // zero hist: 8KB / 256 threads = two uint4 stores each
    ((uint4*)hist)[t]      = make_uint4(0, 0, 0, 0);
    ((uint4*)hist)[t + NT] = make_uint4(0, 0, 0, 0);
    __syncthreads();

    // monotone bucket floor((x+8)*64) clamped: cross-bucket part exact;
    // same-bucket pairs dropped (bias ~2e-5 rel, see analysis).
    const int k0 = max(0, min(NBUK - 1, __float2int_rd((x0 + 8.0f) * 64.0f)));
    const int k1 = max(0, min(NBUK - 1, __float2int_rd((x1 + 8.0f) * 64.0f)));

    if (!p0) {
        const float xc = fminf(fmaxf(x0, -15.9f), 15.9f);
        atomicAdd(&hist[k0], (1ULL << CNT_SHIFT)
                             | (unsigned long long)(unsigned)((xc + 16.0f) * FIX_SCALE));
    }
    if (!p1) {
        const float xc = fminf(fmaxf(x1, -15.9f), 15.9f);
        atomicAdd(&hist[k1], (1ULL << CNT_SHIFT)
                             | (unsigned long long)(unsigned)((xc + 16.0f) * FIX_SCALE));
    }
    __syncthreads();

    // ---- scan: thread owns buckets 4t..4t+3 ----
    ulonglong2 A = ((ulonglong2*)hist)[2 * t];
    ulonglong2 B = ((ulonglong2*)hist)[2 * t + 1];
    const unsigned long long i0 = A.x;
    const unsigned long long i1 = i0 + A.y;
    const unsigned long long i2 = i1 + B.x;
    const unsigned long long i3 = i2 + B.y;

    unsigned long long inc = i3;
    #pragma unroll
    for (int o = 1; o < 32; o <<= 1) {
        unsigned long long n = __shfl_up_sync(FULL, inc, o);
        if (lane >= o) inc += n;
    }
    if (lane == 31) wsc[w] = inc;
    __syncthreads();
    if (t < 32) {
        unsigned long long ci = (t < NW) ? wsc[t] : 0ULL;
        #pragma unroll
        for (int o = 1; o < NW; o <<= 1) {
            unsigned long long n = __shfl_up_sync(FULL, ci, o);
            if (lane >= o) ci += n;
        }
        if (t < NW) wsc[t] = ci;
    }
    __syncthreads();

    const unsigned long long base = (inc - i3) + ((w > 0) ? wsc[w - 1] : 0ULL);
    const unsigned long long tot  = wsc[NW - 1];
    const int nn = (int)(tot >> CNT_SHIFT);

    // store per-bucket SUFFIX (strictly-higher buckets), exact field-wise
    ulonglong2 S0, S1;
    S0.x = tot - (base + i0);
    S0.y = tot - (base + i1);
    S1.x = tot - (base + i2);
    S1.y = tot - (base + i3);
    ((ulonglong2*)hist)[2 * t]     = S0;
    ((ulonglong2*)hist)[2 * t + 1] = S1;
    __syncthreads();

    // ---- eval: sum over negs in higher buckets of (nj - si) ----
    float total = 0.f;
    if (p0) {
        const unsigned long long sp64 = hist[k0];
        const float sC = (float)(int)(sp64 >> CNT_SHIFT);
        const float sS = (float)(long long)(sp64 & LOW_MASK) * FIX_INVF - 16.0f * sC;
        total += sS - sC * s0;
    }
    if (p1) {
        const unsigned long long sp64 = hist[k1];
        const float sC = (float)(int)(sp64 >> CNT_SHIFT);
        const float sS = (float)(long long)(sp64 & LOW_MASK) * FIX_INVF - 16.0f * sC;
        total += sS - sC * s1;
    }

    // ---- deterministic CTA reduction ----
    #pragma unroll
    for (int o = 16; o > 0; o >>= 1)
        total += __shfl_down_sync(FULL, total, o);
    if (lane == 0) warp_sums[w] = total;
    __syncthreads();

    if (t < 32) {
        float v = (t < NW) ? warp_sums[t] : 0.f;
        #pragma unroll
        for (int o = NW / 2; o > 0; o >>= 1)
            v += __shfl_down_sync(FULL, v, o);
        if (t == 0) {
            const int   np    = M - nn;
            const bool  valid = (np > 0) && (nn > 0);
            const float cntf  = (float)np * (float)nn;
            float2 p;
            p.x = valid ? (v / cntf) : 0.f;
            p.y = valid ? 1.f : 0.f;
            g_partials[b] = p;
            __threadfence();
            int cc = atomicAdd(&g_count, 1);
            is_last = (cc == NBLK - 1);
        }
    }
    __syncthreads();

    // ---- last block: fixed-order global reduction + finalize ----
    if (is_last) {
        float m = 0.f, vv = 0.f;
        #pragma unroll
        for (int i = t; i < NBLK; i += NT) {
            float2 p = g_partials[i];
            m  += p.x;
            vv += p.y;
        }
        #pragma unroll
        for (int o = 16; o > 0; o >>= 1) {
            m  += __shfl_down_sync(FULL, m, o);
            vv += __shfl_down_sync(FULL, vv, o);
        }
        if (lane == 0) { warp_sums[w] = m; wred[w] = vv; }
        __syncthreads();
        if (t < 32) {
            m  = (t < NW) ? warp_sums[t] : 0.f;
            vv = (t < NW) ? wred[t] : 0.f;
            #pragma unroll
            for (int o = NW / 2; o > 0; o >>= 1) {
                m  += __shfl_down_sync(FULL, m, o);
                vv += __shfl_down_sync(FULL, vv, o);
            }
            if (t == 0) {
                out[0] = m / vv;
                g_count = 0;
            }
        }
    }
}

extern "C" void kernel_launch(void* const* d_in, const int* in_sizes, int n_in,
                              void* d_out, int out_size) {
    const float* scores = (const float*)d_in[0];
    const int*   labels = (const int*)d_in[1];
    float* out = (float*)d_out;

    dim3 pblk(32, 8), pgrd(16, 16);
    prep_kernel<<<pgrd, pblk>>>(scores, labels);
    side_kernel<<<NBLK, NT>>>(scores, out);
}